// round 6
// baseline (speedup 1.0000x reference)
#include <cuda_runtime.h>

// ManualGRU: B=256, S=2048, I=64, H=128
// out = [hidden_seq (B,S,H) fp32][h_last (B,H) fp32]

#define BB   256
#define SS   2048
#define II   64
#define HH   128
#define G3   384      // 3*H

// Scratch: from_input laid out as [s][b][384] so the scan reads coalesced rows.
__device__ float g_xin[(size_t)SS * BB * G3];

// ---------------- packed f32x2 helpers ----------------
__device__ __forceinline__ unsigned long long pk2(float lo, float hi) {
    unsigned long long r;
    asm("mov.b64 %0, {%1, %2};" : "=l"(r)
        : "r"(__float_as_uint(lo)), "r"(__float_as_uint(hi)));
    return r;
}
__device__ __forceinline__ unsigned long long f2fma(unsigned long long a,
                                                    unsigned long long b,
                                                    unsigned long long c) {
    unsigned long long d;
    asm("fma.rn.f32x2 %0, %1, %2, %3;" : "=l"(d) : "l"(a), "l"(b), "l"(c));
    return d;
}
__device__ __forceinline__ float psum2(unsigned long long p) {
    unsigned int lo, hi;
    asm("mov.b64 {%0, %1}, %2;" : "=r"(lo), "=r"(hi) : "l"(p));
    return __uint_as_float(lo) + __uint_as_float(hi);
}

__device__ __forceinline__ float fast_sigmoid(float x) {
    float e = __expf(-x);               // x very negative -> e = inf -> result 0 (ok)
    return __fdividef(1.0f, 1.0f + e);
}
__device__ __forceinline__ float fast_tanh(float x) {
    float ax = fabsf(x);
    float e  = __expf(-2.0f * ax);      // e in (0,1]
    float t  = __fdividef(1.0f - e, 1.0f + e);
    return copysignf(t, x);
}

// ---------------------------------------------------------------------------
// Phase 1: from_input = inputs @ W_in + b_in   (rows = b*S+s, cols = 384)
// Tile: 128 rows x 384 cols per block, col-chunks of 64.
// Output scattered to g_xin[s][b][col] (16B-contiguous per thread-row write).
// ---------------------------------------------------------------------------
__global__ void __launch_bounds__(256, 1)
k_in_gemm(const float* __restrict__ X, const float* __restrict__ W,
          const float* __restrict__ bias) {
    __shared__ float As[128 * 64];   // 32 KB
    __shared__ float Ws[64 * 64];    // 16 KB  (total 48 KB)

    const int tid  = threadIdx.x;
    const int row0 = blockIdx.x * 128;          // global row = b*S + s
    const int bb   = row0 >> 11;                // batch (tile never spans batch: 2048 % 128 == 0)
    const int s0   = row0 & 2047;

    // Load A tile (128x64 fp32, contiguous 32KB) via float4, fully coalesced.
    {
        const float4* Xv  = (const float4*)(X + (size_t)row0 * II);
        float4*       Av  = (float4*)As;
#pragma unroll
        for (int i = 0; i < 8; i++) Av[tid + 256 * i] = Xv[tid + 256 * i];
    }

    const int tx = tid & 15;     // 16 column groups of 4 cols (2 f32x2 pairs)
    const int ty = tid >> 4;     // 16 row groups of 8 rows

    for (int cc = 0; cc < 6; cc++) {
        __syncthreads();  // protects Ws reuse + (first iter) A-tile completion
        // Load W chunk: 64 k x 64 cols
#pragma unroll
        for (int i = 0; i < 16; i++) {
            int idx = tid + 256 * i;
            Ws[idx] = W[(idx >> 6) * G3 + cc * 64 + (idx & 63)];
        }
        __syncthreads();

        unsigned long long acc[8][2];
#pragma unroll
        for (int r = 0; r < 8; r++) { acc[r][0] = 0ull; acc[r][1] = 0ull; }

#pragma unroll 8
        for (int k = 0; k < 64; k++) {
            unsigned long long bp0 = *(const unsigned long long*)&Ws[k * 64 + tx * 4];
            unsigned long long bp1 = *(const unsigned long long*)&Ws[k * 64 + tx * 4 + 2];
#pragma unroll
            for (int r = 0; r < 8; r++) {
                float a = As[(ty * 8 + r) * 64 + k];
                unsigned long long ap = pk2(a, a);
                acc[r][0] = f2fma(ap, bp0, acc[r][0]);
                acc[r][1] = f2fma(ap, bp1, acc[r][1]);
            }
        }

        // Epilogue: add bias, write 4 contiguous cols per row to g_xin[s][b][col]
        const int colbase = cc * 64 + tx * 4;
        const float bi0 = bias[colbase + 0];
        const float bi1 = bias[colbase + 1];
        const float bi2 = bias[colbase + 2];
        const float bi3 = bias[colbase + 3];
#pragma unroll
        for (int r = 0; r < 8; r++) {
            unsigned int l0, h0, l1, h1;
            asm("mov.b64 {%0, %1}, %2;" : "=r"(l0), "=r"(h0) : "l"(acc[r][0]));
            asm("mov.b64 {%0, %1}, %2;" : "=r"(l1), "=r"(h1) : "l"(acc[r][1]));
            float4 o;
            o.x = __uint_as_float(l0) + bi0;
            o.y = __uint_as_float(h0) + bi1;
            o.z = __uint_as_float(l1) + bi2;
            o.w = __uint_as_float(h1) + bi3;
            int s = s0 + ty * 8 + r;
            *(float4*)&g_xin[((size_t)s * BB + bb) * G3 + colbase] = o;
        }
    }
}

// ---------------------------------------------------------------------------
// Phase 2: the sequential GRU scan.
// 128 CTAs, each owns 2 batches. 384 threads; thread t owns column t of W_h
// (128 weights = 64 packed f32x2 pairs, register-resident).
//   cols [0,128)   -> r gate
//   cols [128,256) -> z gate
//   cols [256,384) -> n pre-activation (hn)
// ---------------------------------------------------------------------------
__global__ void __launch_bounds__(384, 1)
k_gru(const float* __restrict__ Wh, const float* __restrict__ bias,
      float* __restrict__ out) {
    __shared__ __align__(16) float h_sm[2][HH];
    __shared__ float r_sm[2][HH];
    __shared__ float z_sm[2][HH];

    const int t  = threadIdx.x;           // 0..383 (output column)
    const int b0 = blockIdx.x * 2;

    // Per-thread weight column (pack consecutive k as f32x2 pairs)
    unsigned long long wreg[64];
#pragma unroll
    for (int i = 0; i < 64; i++) {
        float w0 = Wh[(2 * i) * G3 + t];
        float w1 = Wh[(2 * i + 1) * G3 + t];
        wreg[i] = pk2(w0, w1);
    }
    const float bh = bias[G3 + t];        // b_h[t]

    if (t < HH) { h_sm[0][t] = 0.0f; h_sm[1][t] = 0.0f; }

    // Preload x for step 0
    float xc0 = g_xin[(0 * BB + b0) * G3 + t];
    float xc1 = g_xin[(0 * BB + b0) * G3 + t + G3];
    __syncthreads();

    const unsigned long long zz = pk2(0.0f, 0.0f);

    for (int st = 0; st < SS; st++) {
        // Prefetch x for step st+1 (consumed at end of this iteration)
        float xp0 = 0.0f, xp1 = 0.0f;
        if (st + 1 < SS) {
            int base = ((st + 1) * BB + b0) * G3 + t;
            xp0 = g_xin[base];
            xp1 = g_xin[base + G3];
        }

        // ---- matvec: v_b = b_h[t] + sum_k h_b[k] * W_h[k][t] ----
        unsigned long long a0 = pk2(bh, 0.0f), c0 = zz;
        unsigned long long a1 = pk2(bh, 0.0f), c1 = zz;
        const ulonglong2* h0v = (const ulonglong2*)&h_sm[0][0];
        const ulonglong2* h1v = (const ulonglong2*)&h_sm[1][0];
#pragma unroll
        for (int i = 0; i < 32; i++) {
            ulonglong2 hv0 = h0v[i];   // h0[4i..4i+3] as two f32x2 (broadcast LDS.128)
            ulonglong2 hv1 = h1v[i];
            a0 = f2fma(wreg[2 * i],     hv0.x, a0);
            c0 = f2fma(wreg[2 * i + 1], hv0.y, c0);
            a1 = f2fma(wreg[2 * i],     hv1.x, a1);
            c1 = f2fma(wreg[2 * i + 1], hv1.y, c1);
        }
        float v0 = psum2(a0) + psum2(c0);
        float v1 = psum2(a1) + psum2(c1);

        // ---- r/z gates into smem ----
        if (t < 256) {
            float g0 = fast_sigmoid(v0 + xc0);
            float g1 = fast_sigmoid(v1 + xc1);
            if (t < HH) { r_sm[0][t] = g0;        r_sm[1][t] = g1; }
            else        { z_sm[0][t - HH] = g0;   z_sm[1][t - HH] = g1; }
        }
        __syncthreads();

        // ---- n gate + state update (threads 256..383; j = t-256), v = hn ----
        if (t >= 256) {
            int j = t - 256;
            float r0 = r_sm[0][j], z0 = z_sm[0][j], ho0 = h_sm[0][j];
            float n0 = fast_tanh(xc0 + r0 * v0);
            float hn0 = n0 + z0 * (ho0 - n0);         // (1-z)n + z h
            h_sm[0][j] = hn0;
            out[((size_t)b0 * SS + st) * HH + j] = hn0;

            float r1 = r_sm[1][j], z1 = z_sm[1][j], ho1 = h_sm[1][j];
            float n1 = fast_tanh(xc1 + r1 * v1);
            float hn1 = n1 + z1 * (ho1 - n1);
            h_sm[1][j] = hn1;
            out[((size_t)(b0 + 1) * SS + st) * HH + j] = hn1;
        }

        xc0 = xp0;
        xc1 = xp1;
        __syncthreads();   // h_sm update visible before next matvec
    }

    // h_last
    if (t < HH) {
        const size_t off = (size_t)BB * SS * HH;
        out[off + (size_t)b0 * HH + t]       = h_sm[0][t];
        out[off + (size_t)(b0 + 1) * HH + t] = h_sm[1][t];
    }
}

// ---------------------------------------------------------------------------
extern "C" void kernel_launch(void* const* d_in, const int* in_sizes, int n_in,
                              void* d_out, int out_size) {
    (void)in_sizes; (void)n_in; (void)out_size;
    const float* X    = (const float*)d_in[0];   // inputs (B,S,I)
    const float* Win  = (const float*)d_in[1];   // W_in (I, 3H)
    const float* Wh   = (const float*)d_in[2];   // W_h  (H, 3H)
    const float* bias = (const float*)d_in[3];   // (6H,)
    float* out = (float*)d_out;

    k_in_gemm<<<(BB * SS) / 128, 256>>>(X, Win, bias);
    k_gru<<<BB / 2, 384>>>(Wh, bias, out);
}

// round 9
// speedup vs baseline: 1.1092x; 1.1092x over previous
#include <cuda_runtime.h>

// ManualGRU: B=256, S=2048, I=64, H=128
// out = [hidden_seq (B,S,H) fp32][h_last (B,H) fp32]

#define BB   256
#define SS   2048
#define II   64
#define HH   128
#define G3   384      // 3*H

// Scratch: from_input laid out as [s][b][384] so the scan reads coalesced rows.
__device__ float g_xin[(size_t)SS * BB * G3];

// ---------------- packed f32x2 helpers ----------------
__device__ __forceinline__ unsigned long long pk2(float lo, float hi) {
    unsigned long long r;
    asm("mov.b64 %0, {%1, %2};" : "=l"(r)
        : "r"(__float_as_uint(lo)), "r"(__float_as_uint(hi)));
    return r;
}
__device__ __forceinline__ unsigned long long f2fma(unsigned long long a,
                                                    unsigned long long b,
                                                    unsigned long long c) {
    unsigned long long d;
    asm("fma.rn.f32x2 %0, %1, %2, %3;" : "=l"(d) : "l"(a), "l"(b), "l"(c));
    return d;
}
__device__ __forceinline__ float psum2(unsigned long long p) {
    unsigned int lo, hi;
    asm("mov.b64 {%0, %1}, %2;" : "=r"(lo), "=r"(hi) : "l"(p));
    return __uint_as_float(lo) + __uint_as_float(hi);
}

__device__ __forceinline__ float fast_sigmoid(float x) {
    float e = __expf(-x);
    return __fdividef(1.0f, 1.0f + e);
}
__device__ __forceinline__ float fast_tanh(float x) {
    float ax = fabsf(x);
    float e  = __expf(-2.0f * ax);
    float t  = __fdividef(1.0f - e, 1.0f + e);
    return copysignf(t, x);
}

// ---------------------------------------------------------------------------
// Phase 1: from_input = inputs @ W_in + b_in   (rows = b*S+s, cols = 384)
// (unchanged from R5 — tensorization is a future round)
// ---------------------------------------------------------------------------
__global__ void __launch_bounds__(256, 1)
k_in_gemm(const float* __restrict__ X, const float* __restrict__ W,
          const float* __restrict__ bias) {
    __shared__ float As[128 * 64];   // 32 KB
    __shared__ float Ws[64 * 64];    // 16 KB

    const int tid  = threadIdx.x;
    const int row0 = blockIdx.x * 128;
    const int bb   = row0 >> 11;
    const int s0   = row0 & 2047;

    {
        const float4* Xv  = (const float4*)(X + (size_t)row0 * II);
        float4*       Av  = (float4*)As;
#pragma unroll
        for (int i = 0; i < 8; i++) Av[tid + 256 * i] = Xv[tid + 256 * i];
    }

    const int tx = tid & 15;
    const int ty = tid >> 4;

    for (int cc = 0; cc < 6; cc++) {
        __syncthreads();
#pragma unroll
        for (int i = 0; i < 16; i++) {
            int idx = tid + 256 * i;
            Ws[idx] = W[(idx >> 6) * G3 + cc * 64 + (idx & 63)];
        }
        __syncthreads();

        unsigned long long acc[8][2];
#pragma unroll
        for (int r = 0; r < 8; r++) { acc[r][0] = 0ull; acc[r][1] = 0ull; }

#pragma unroll 8
        for (int k = 0; k < 64; k++) {
            unsigned long long bp0 = *(const unsigned long long*)&Ws[k * 64 + tx * 4];
            unsigned long long bp1 = *(const unsigned long long*)&Ws[k * 64 + tx * 4 + 2];
#pragma unroll
            for (int r = 0; r < 8; r++) {
                float a = As[(ty * 8 + r) * 64 + k];
                unsigned long long ap = pk2(a, a);
                acc[r][0] = f2fma(ap, bp0, acc[r][0]);
                acc[r][1] = f2fma(ap, bp1, acc[r][1]);
            }
        }

        const int colbase = cc * 64 + tx * 4;
        const float bi0 = bias[colbase + 0];
        const float bi1 = bias[colbase + 1];
        const float bi2 = bias[colbase + 2];
        const float bi3 = bias[colbase + 3];
#pragma unroll
        for (int r = 0; r < 8; r++) {
            unsigned int l0, h0, l1, h1;
            asm("mov.b64 {%0, %1}, %2;" : "=r"(l0), "=r"(h0) : "l"(acc[r][0]));
            asm("mov.b64 {%0, %1}, %2;" : "=r"(l1), "=r"(h1) : "l"(acc[r][1]));
            float4 o;
            o.x = __uint_as_float(l0) + bi0;
            o.y = __uint_as_float(h0) + bi1;
            o.z = __uint_as_float(l1) + bi2;
            o.w = __uint_as_float(h1) + bi3;
            int s = s0 + ty * 8 + r;
            *(float4*)&g_xin[((size_t)s * BB + bb) * G3 + colbase] = o;
        }
    }
}

// ---------------------------------------------------------------------------
// Phase 2: GRU scan, k-split layout.
// 128 CTAs x 384 threads, 2 batches per CTA.
// Thread t: cg = t%96 (owns cols 4cg..4cg+3), kg = t/96 (k-slice 32kg..32kg+31).
// Matvec: each thread computes 4cols x 2batches partial dots over its 32-k
// slice (16 LDS.128 of h instead of 64), stores partials via 2x STS.128.
// After barrier, the 128 n-threads (t>=256) reduce partials, compute all
// three gates + state update, write h and out. Second barrier publishes h.
// ---------------------------------------------------------------------------
__global__ void __launch_bounds__(384, 1)
k_gru(const float* __restrict__ Wh, const float* __restrict__ bias,
      float* __restrict__ out) {
    __shared__ __align__(16) float h_sm[2][HH];        // 1 KB
    __shared__ __align__(16) float part[4][2][G3];     // 12 KB  [kg][b][col]

    const int t  = threadIdx.x;
    const int b0 = blockIdx.x * 2;
    const int cg = t % 96;
    const int kg = t / 96;            // 0..3
    const int col0 = 4 * cg;
    const int k0   = 32 * kg;

    // Register-resident weight slice: wreg[c][i] = {Wh[k0+2i][col0+c], Wh[k0+2i+1][col0+c]}
    unsigned long long wreg[4][16];
#pragma unroll
    for (int i = 0; i < 16; i++) {
        const float* r0 = Wh + (size_t)(k0 + 2 * i) * G3 + col0;
        const float* r1 = r0 + G3;
#pragma unroll
        for (int c = 0; c < 4; c++) wreg[c][i] = pk2(r0[c], r1[c]);
    }

    // n-thread (updater) state
    const int j = t - 256;            // valid when t >= 256
    float bhr = 0.f, bhz = 0.f, bhn = 0.f;
    float xr0c = 0.f, xz0c = 0.f, xn0c = 0.f, xr1c = 0.f, xz1c = 0.f, xn1c = 0.f;
    if (t >= 256) {
        bhr = bias[G3 + j];
        bhz = bias[G3 + 128 + j];
        bhn = bias[G3 + 256 + j];
        const float* xb = g_xin + (size_t)(0 * BB + b0) * G3;
        xr0c = xb[j];        xz0c = xb[128 + j];        xn0c = xb[256 + j];
        xr1c = xb[G3 + j];   xz1c = xb[G3 + 128 + j];   xn1c = xb[G3 + 256 + j];
    }

    if (t < HH) { h_sm[0][t] = 0.0f; h_sm[1][t] = 0.0f; }
    __syncthreads();

    for (int st = 0; st < SS; st++) {
        // Prefetch next step's x (n-threads only)
        float xr0p = 0.f, xz0p = 0.f, xn0p = 0.f, xr1p = 0.f, xz1p = 0.f, xn1p = 0.f;
        if (t >= 256 && st + 1 < SS) {
            const float* xb = g_xin + (size_t)((st + 1) * BB + b0) * G3;
            xr0p = xb[j];        xz0p = xb[128 + j];        xn0p = xb[256 + j];
            xr1p = xb[G3 + j];   xz1p = xb[G3 + 128 + j];   xn1p = xb[G3 + 256 + j];
        }

        // ---- matvec partials: 4 cols x 2 batches over k-slice [k0, k0+32) ----
        unsigned long long acc[4][2];
#pragma unroll
        for (int c = 0; c < 4; c++) { acc[c][0] = 0ull; acc[c][1] = 0ull; }

        const ulonglong2* hv0 = (const ulonglong2*)&h_sm[0][k0];  // 8 x 16B
        const ulonglong2* hv1 = (const ulonglong2*)&h_sm[1][k0];
#pragma unroll
        for (int q = 0; q < 8; q++) {
            ulonglong2 a = hv0[q];     // {h0[k0+4q..+1]},{h0[k0+4q+2..+3]}
            ulonglong2 b = hv1[q];
#pragma unroll
            for (int c = 0; c < 4; c++) {
                acc[c][0] = f2fma(wreg[c][2 * q],     a.x, acc[c][0]);
                acc[c][0] = f2fma(wreg[c][2 * q + 1], a.y, acc[c][0]);
                acc[c][1] = f2fma(wreg[c][2 * q],     b.x, acc[c][1]);
                acc[c][1] = f2fma(wreg[c][2 * q + 1], b.y, acc[c][1]);
            }
        }

        {
            float4 p0, p1;
            p0.x = psum2(acc[0][0]); p0.y = psum2(acc[1][0]);
            p0.z = psum2(acc[2][0]); p0.w = psum2(acc[3][0]);
            p1.x = psum2(acc[0][1]); p1.y = psum2(acc[1][1]);
            p1.z = psum2(acc[2][1]); p1.w = psum2(acc[3][1]);
            *(float4*)&part[kg][0][col0] = p0;
            *(float4*)&part[kg][1][col0] = p1;
        }
        __syncthreads();

        // ---- gates + state update: threads 256..383 (j = t-256) ----
        if (t >= 256) {
            // batch 0
            float vr0 = part[0][0][j] + part[1][0][j] + part[2][0][j] + part[3][0][j] + bhr;
            float vz0 = part[0][0][128 + j] + part[1][0][128 + j]
                      + part[2][0][128 + j] + part[3][0][128 + j] + bhz;
            float vn0 = part[0][0][256 + j] + part[1][0][256 + j]
                      + part[2][0][256 + j] + part[3][0][256 + j] + bhn;
            // batch 1
            float vr1 = part[0][1][j] + part[1][1][j] + part[2][1][j] + part[3][1][j] + bhr;
            float vz1 = part[0][1][128 + j] + part[1][1][128 + j]
                      + part[2][1][128 + j] + part[3][1][128 + j] + bhz;
            float vn1 = part[0][1][256 + j] + part[1][1][256 + j]
                      + part[2][1][256 + j] + part[3][1][256 + j] + bhn;

            float r0 = fast_sigmoid(xr0c + vr0);
            float z0 = fast_sigmoid(xz0c + vz0);
            float r1 = fast_sigmoid(xr1c + vr1);
            float z1 = fast_sigmoid(xz1c + vz1);

            float n0 = fast_tanh(xn0c + r0 * vn0);
            float n1 = fast_tanh(xn1c + r1 * vn1);

            float ho0 = h_sm[0][j];
            float ho1 = h_sm[1][j];
            float hn0 = n0 + z0 * (ho0 - n0);       // (1-z)n + z h
            float hn1 = n1 + z1 * (ho1 - n1);
            h_sm[0][j] = hn0;
            h_sm[1][j] = hn1;
            out[((size_t)b0 * SS + st) * HH + j]       = hn0;
            out[((size_t)(b0 + 1) * SS + st) * HH + j] = hn1;

            xr0c = xr0p; xz0c = xz0p; xn0c = xn0p;
            xr1c = xr1p; xz1c = xz1p; xn1c = xn1p;
        }
        __syncthreads();   // publish h for next step's matvec
    }

    // h_last
    if (t < HH) {
        const size_t off = (size_t)BB * SS * HH;
        out[off + (size_t)b0 * HH + t]       = h_sm[0][t];
        out[off + (size_t)(b0 + 1) * HH + t] = h_sm[1][t];
    }
}

// ---------------------------------------------------------------------------
extern "C" void kernel_launch(void* const* d_in, const int* in_sizes, int n_in,
                              void* d_out, int out_size) {
    (void)in_sizes; (void)n_in; (void)out_size;
    const float* X    = (const float*)d_in[0];   // inputs (B,S,I)
    const float* Win  = (const float*)d_in[1];   // W_in (I, 3H)
    const float* Wh   = (const float*)d_in[2];   // W_h  (H, 3H)
    const float* bias = (const float*)d_in[3];   // (6H,)
    float* out = (float*)d_out;

    k_in_gemm<<<(BB * SS) / 128, 256>>>(X, Win, bias);
    k_gru<<<BB / 2, 384>>>(Wh, bias, out);
}